// round 1
// baseline (speedup 1.0000x reference)
#include <cuda_runtime.h>
#include <math.h>

// Problem dims (compile-time)
#define T_STEPS 30
#define NB      32
#define S_MEM   50
#define HID     512
#define EMB     512
#define LATD    64
#define VOCAB   32000
#define GIN     1600      // E + MC + MF + LAT
#define G3H     1536      // 3*H

// ---------------- device scratch (no cudaMalloc allowed) ----------------
__device__ float g_memT[2][S_MEM][HID][NB];   // [side][s][m][b]  transposed memories
__device__ float g_KT  [2][S_MEM][HID][NB];   // attention keys  (mem @ W_m.T + b_m)
__device__ float g_embT[T_STEPS][EMB][NB];    // embedded input tokens, transposed
__device__ float g_latT[LATD][NB];
__device__ float g_hT  [2][HID][NB];          // ping-pong hidden state, transposed
__device__ float g_qT  [2][HID][NB];          // attention queries (c=0,f=1)
__device__ float g_S4  [2][S_MEM][4][NB];     // partial scores (4 d-quarters)
__device__ float g_ctxT[2][HID][NB];          // contexts (contiguous => [1024][NB])
__device__ float g_GIc [T_STEPS][G3H][NB];    // precomputed gi from emb+latent+b_ih
__device__ float g_Hout[T_STEPS * NB * HID];  // hidden history for final projection

// ---------------- precompute kernels ----------------

// transpose memories: [s][b][m] -> [side][s][m][b]
__global__ void k_prep_mem(const float* __restrict__ cmem, const float* __restrict__ fmem) {
    int i = blockIdx.x * blockDim.x + threadIdx.x;
    const int total = 2 * S_MEM * HID * NB;
    if (i >= total) return;
    int b = i & 31;
    int m = (i >> 5) & 511;
    int s = (i >> 14) % S_MEM;
    int side = i / (S_MEM * HID * NB);
    const float* src = side ? fmem : cmem;
    g_memT[side][s][m][b] = src[(s * NB + b) * HID + m];
}

// embT (with teacher-forced tokens: [SOS=1, target[:-1]]), h0 transpose, latent transpose
__global__ void k_prep_misc(const float* __restrict__ hidden, const float* __restrict__ latent,
                            const float* __restrict__ emb, const int* __restrict__ target) {
    int i = blockIdx.x * blockDim.x + threadIdx.x;
    const int N1 = T_STEPS * EMB * NB;
    const int N2 = HID * NB;
    const int N3 = LATD * NB;
    if (i < N1) {
        int b = i & 31; int e = (i >> 5) & 511; int t = i >> 14;
        int tok = (t == 0) ? 1 : target[(t - 1) * NB + b];
        g_embT[t][e][b] = emb[(size_t)tok * EMB + e];
    } else if (i < N1 + N2) {
        int j = i - N1; int b = j & 31; int m = j >> 5;
        g_hT[0][m][b] = hidden[b * HID + m];
    } else if (i < N1 + N2 + N3) {
        int j = i - N1 - N2; int b = j & 31; int l = j >> 5;
        g_latT[l][b] = latent[b * LATD + l];
    }
}

// K = memory @ W_m.T + b_m  for both sides. warp = (side, s, 4 d's), lane = b
__global__ void __launch_bounds__(256) k_KT(const float* __restrict__ cW, const float* __restrict__ cb,
                                            const float* __restrict__ fW, const float* __restrict__ fb) {
    int wid  = (blockIdx.x * blockDim.x + threadIdx.x) >> 5;
    int lane = threadIdx.x & 31;
    int dgrp = wid & 127;
    int s    = (wid >> 7) % S_MEM;
    int side = wid / (S_MEM * 128);
    if (side >= 2) return;
    const float* W = side ? fW : cW;
    const float* bb = side ? fb : cb;
    int d0 = dgrp * 4;
    float a0 = bb[d0], a1 = bb[d0+1], a2 = bb[d0+2], a3 = bb[d0+3];
    const float* x = &g_memT[side][s][0][lane];
    #pragma unroll 4
    for (int m = 0; m < HID; m += 4) {
        float4 w0 = *(const float4*)&W[(d0+0)*HID + m];
        float4 w1 = *(const float4*)&W[(d0+1)*HID + m];
        float4 w2 = *(const float4*)&W[(d0+2)*HID + m];
        float4 w3 = *(const float4*)&W[(d0+3)*HID + m];
        float x0 = x[(m+0)*NB], x1 = x[(m+1)*NB], x2 = x[(m+2)*NB], x3 = x[(m+3)*NB];
        a0 += w0.x*x0 + w0.y*x1 + w0.z*x2 + w0.w*x3;
        a1 += w1.x*x0 + w1.y*x1 + w1.z*x2 + w1.w*x3;
        a2 += w2.x*x0 + w2.y*x1 + w2.z*x2 + w2.w*x3;
        a3 += w3.x*x0 + w3.y*x1 + w3.z*x2 + w3.w*x3;
    }
    g_KT[side][s][d0+0][lane] = a0;
    g_KT[side][s][d0+1][lane] = a1;
    g_KT[side][s][d0+2][lane] = a2;
    g_KT[side][s][d0+3][lane] = a3;
}

// GI_const[t][j][b] = b_ih[j] + emb . W_ih[j, 0:512] + latent . W_ih[j, 1536:1600]
__global__ void __launch_bounds__(256) k_GIc(const float* __restrict__ W_ih, const float* __restrict__ b_ih) {
    int wid  = (blockIdx.x * blockDim.x + threadIdx.x) >> 5;
    int lane = threadIdx.x & 31;
    int jgrp = wid % 384;
    int t    = wid / 384;
    if (t >= T_STEPS) return;
    int j0 = jgrp * 4;
    float a0 = b_ih[j0], a1 = b_ih[j0+1], a2 = b_ih[j0+2], a3 = b_ih[j0+3];
    const float* r0 = W_ih + (size_t)(j0+0)*GIN;
    const float* r1 = W_ih + (size_t)(j0+1)*GIN;
    const float* r2 = W_ih + (size_t)(j0+2)*GIN;
    const float* r3 = W_ih + (size_t)(j0+3)*GIN;
    #pragma unroll 4
    for (int e = 0; e < EMB; e += 4) {
        float4 w0 = *(const float4*)&r0[e];
        float4 w1 = *(const float4*)&r1[e];
        float4 w2 = *(const float4*)&r2[e];
        float4 w3 = *(const float4*)&r3[e];
        float x0 = g_embT[t][e+0][lane], x1 = g_embT[t][e+1][lane];
        float x2 = g_embT[t][e+2][lane], x3 = g_embT[t][e+3][lane];
        a0 += w0.x*x0 + w0.y*x1 + w0.z*x2 + w0.w*x3;
        a1 += w1.x*x0 + w1.y*x1 + w1.z*x2 + w1.w*x3;
        a2 += w2.x*x0 + w2.y*x1 + w2.z*x2 + w2.w*x3;
        a3 += w3.x*x0 + w3.y*x1 + w3.z*x2 + w3.w*x3;
    }
    #pragma unroll
    for (int l = 0; l < LATD; l += 4) {
        float4 w0 = *(const float4*)&r0[1536 + l];
        float4 w1 = *(const float4*)&r1[1536 + l];
        float4 w2 = *(const float4*)&r2[1536 + l];
        float4 w3 = *(const float4*)&r3[1536 + l];
        float x0 = g_latT[l+0][lane], x1 = g_latT[l+1][lane];
        float x2 = g_latT[l+2][lane], x3 = g_latT[l+3][lane];
        a0 += w0.x*x0 + w0.y*x1 + w0.z*x2 + w0.w*x3;
        a1 += w1.x*x0 + w1.y*x1 + w1.z*x2 + w1.w*x3;
        a2 += w2.x*x0 + w2.y*x1 + w2.z*x2 + w2.w*x3;
        a3 += w3.x*x0 + w3.y*x1 + w3.z*x2 + w3.w*x3;
    }
    g_GIc[t][j0+0][lane] = a0;
    g_GIc[t][j0+1][lane] = a1;
    g_GIc[t][j0+2][lane] = a2;
    g_GIc[t][j0+3][lane] = a3;
}

// ---------------- per-step kernels ----------------

// q = h @ W_h.T + b_h for both sides. warp = (side, 4 d's), lane = b
__global__ void __launch_bounds__(256) k_q(int t,
        const float* __restrict__ cW, const float* __restrict__ cb,
        const float* __restrict__ fW, const float* __restrict__ fb) {
    int wid  = (blockIdx.x * blockDim.x + threadIdx.x) >> 5;
    int lane = threadIdx.x & 31;
    int dgrp = wid & 127;
    int side = wid >> 7;
    if (side >= 2) return;
    const float* W = side ? fW : cW;
    const float* bb = side ? fb : cb;
    int d0 = dgrp * 4;
    float a0 = bb[d0], a1 = bb[d0+1], a2 = bb[d0+2], a3 = bb[d0+3];
    const float* x = &g_hT[t & 1][0][0];
    #pragma unroll 4
    for (int m = 0; m < HID; m += 4) {
        float4 w0 = *(const float4*)&W[(d0+0)*HID + m];
        float4 w1 = *(const float4*)&W[(d0+1)*HID + m];
        float4 w2 = *(const float4*)&W[(d0+2)*HID + m];
        float4 w3 = *(const float4*)&W[(d0+3)*HID + m];
        float x0 = x[(m+0)*NB + lane], x1 = x[(m+1)*NB + lane];
        float x2 = x[(m+2)*NB + lane], x3 = x[(m+3)*NB + lane];
        a0 += w0.x*x0 + w0.y*x1 + w0.z*x2 + w0.w*x3;
        a1 += w1.x*x0 + w1.y*x1 + w1.z*x2 + w1.w*x3;
        a2 += w2.x*x0 + w2.y*x1 + w2.z*x2 + w2.w*x3;
        a3 += w3.x*x0 + w3.y*x1 + w3.z*x2 + w3.w*x3;
    }
    g_qT[side][d0+0][lane] = a0;
    g_qT[side][d0+1][lane] = a1;
    g_qT[side][d0+2][lane] = a2;
    g_qT[side][d0+3][lane] = a3;
}

// score partials: S4[side][s][q][b] = sum_{d in quarter q} tanh(q+K) * wo[d]
// (output bias b_o is softmax-invariant, dropped)
__global__ void __launch_bounds__(256) k_score(const float* __restrict__ cWo, const float* __restrict__ fWo) {
    int wid  = (blockIdx.x * blockDim.x + threadIdx.x) >> 5;
    int lane = threadIdx.x & 31;
    if (wid >= 400) return;
    int side = wid / 200;
    int rem  = wid % 200;
    int s = rem >> 2;
    int q = rem & 3;
    const float* wo = side ? fWo : cWo;
    int d0 = q * 128;
    float acc0 = 0.f, acc1 = 0.f;
    const float* qp = &g_qT[side][0][lane];
    const float* kp = &g_KT[side][s][0][lane];
    #pragma unroll 4
    for (int d = d0; d < d0 + 128; d += 2) {
        acc0 += tanhf(qp[d*NB] + kp[d*NB]) * wo[d];
        acc1 += tanhf(qp[(d+1)*NB] + kp[(d+1)*NB]) * wo[d+1];
    }
    g_S4[side][s][q][lane] = acc0 + acc1;
}

// softmax (redundant per warp, in-register) + context reduction. warp = (side, 8 m's)
__global__ void __launch_bounds__(256) k_ctx(const int* __restrict__ cmask, const int* __restrict__ fmask) {
    int wid  = (blockIdx.x * blockDim.x + threadIdx.x) >> 5;
    int lane = threadIdx.x & 31;
    if (wid >= 128) return;
    int side = wid >> 6;
    int m0 = (wid & 63) * 8;
    const int* mask = side ? fmask : cmask;
    float a[S_MEM];
    float mx = -1e30f;
    #pragma unroll
    for (int s = 0; s < S_MEM; s++) {
        float v;
        if (mask[s * NB + lane] == 0) v = -1e30f;
        else v = g_S4[side][s][0][lane] + g_S4[side][s][1][lane]
               + g_S4[side][s][2][lane] + g_S4[side][s][3][lane];
        a[s] = v;
        mx = fmaxf(mx, v);
    }
    float sum = 0.f;
    #pragma unroll
    for (int s = 0; s < S_MEM; s++) { a[s] = expf(a[s] - mx); sum += a[s]; }
    float inv = 1.f / sum;
    #pragma unroll
    for (int j = 0; j < 8; j++) {
        int m = m0 + j;
        float acc = 0.f;
        #pragma unroll
        for (int s = 0; s < S_MEM; s++) acc += a[s] * g_memT[side][s][m][lane];
        g_ctxT[side][m][lane] = acc * inv;
    }
}

// GRU gate GEMVs + pointwise update. block = 4 hidx x 2 k-halves, lane = b
__global__ void __launch_bounds__(256) k_gru(int t,
        const float* __restrict__ W_ih, const float* __restrict__ W_hh,
        const float* __restrict__ b_hh) {
    int w    = threadIdx.x >> 5;
    int lane = threadIdx.x & 31;
    int hloc = w & 3;
    int half = w >> 2;
    int hidx = blockIdx.x * 4 + hloc;

    const float* ctx = &g_ctxT[0][0][0];          // [1024][NB] contiguous
    const float* hTc = &g_hT[t & 1][0][0];        // [512][NB]

    float ir = 0.f, iz = 0.f, inn = 0.f;
    const float* Wr = W_ih + (size_t)(hidx)       * GIN + 512;
    const float* Wz = W_ih + (size_t)(512 + hidx) * GIN + 512;
    const float* Wn = W_ih + (size_t)(1024 + hidx)* GIN + 512;
    int kc0 = half * 512;
    #pragma unroll 4
    for (int k = kc0; k < kc0 + 512; k += 4) {
        float4 wr = *(const float4*)&Wr[k];
        float4 wz = *(const float4*)&Wz[k];
        float4 wn = *(const float4*)&Wn[k];
        float x0 = ctx[(k+0)*NB + lane], x1 = ctx[(k+1)*NB + lane];
        float x2 = ctx[(k+2)*NB + lane], x3 = ctx[(k+3)*NB + lane];
        ir  += wr.x*x0 + wr.y*x1 + wr.z*x2 + wr.w*x3;
        iz  += wz.x*x0 + wz.y*x1 + wz.z*x2 + wz.w*x3;
        inn += wn.x*x0 + wn.y*x1 + wn.z*x2 + wn.w*x3;
    }
    float hr = 0.f, hz = 0.f, hn = 0.f;
    const float* Ur = W_hh + (size_t)(hidx)       * HID;
    const float* Uz = W_hh + (size_t)(512 + hidx) * HID;
    const float* Un = W_hh + (size_t)(1024 + hidx)* HID;
    int kh0 = half * 256;
    #pragma unroll 4
    for (int k = kh0; k < kh0 + 256; k += 4) {
        float4 wr = *(const float4*)&Ur[k];
        float4 wz = *(const float4*)&Uz[k];
        float4 wn = *(const float4*)&Un[k];
        float x0 = hTc[(k+0)*NB + lane], x1 = hTc[(k+1)*NB + lane];
        float x2 = hTc[(k+2)*NB + lane], x3 = hTc[(k+3)*NB + lane];
        hr += wr.x*x0 + wr.y*x1 + wr.z*x2 + wr.w*x3;
        hz += wz.x*x0 + wz.y*x1 + wz.z*x2 + wz.w*x3;
        hn += wn.x*x0 + wn.y*x1 + wn.z*x2 + wn.w*x3;
    }

    __shared__ float red[6][4][NB];
    if (half == 1) {
        red[0][hloc][lane] = ir;  red[1][hloc][lane] = iz;  red[2][hloc][lane] = inn;
        red[3][hloc][lane] = hr;  red[4][hloc][lane] = hz;  red[5][hloc][lane] = hn;
    }
    __syncthreads();
    if (half == 0) {
        ir  += red[0][hloc][lane] + g_GIc[t][hidx][lane];
        iz  += red[1][hloc][lane] + g_GIc[t][512 + hidx][lane];
        inn += red[2][hloc][lane] + g_GIc[t][1024 + hidx][lane];
        hr  += red[3][hloc][lane] + b_hh[hidx];
        hz  += red[4][hloc][lane] + b_hh[512 + hidx];
        hn  += red[5][hloc][lane] + b_hh[1024 + hidx];
        float r = 1.f / (1.f + expf(-(ir + hr)));
        float z = 1.f / (1.f + expf(-(iz + hz)));
        float n = tanhf(inn + r * hn);
        float ho = hTc[hidx * NB + lane];
        float hnew = (1.f - z) * n + z * ho;
        g_hT[(t & 1) ^ 1][hidx][lane] = hnew;
        g_Hout[((size_t)t * NB + lane) * HID + hidx] = hnew;
    }
}

// ---------------- final projection: [960,512] x [512,32000] ----------------
// out[b][t][v] = relu(H[t][b]) . W_proj[v] + b_proj[v]
// 64x128 tile, BK=16, 256 threads, 4x8 micro-tile per thread.
__global__ void __launch_bounds__(256) k_proj(const float* __restrict__ Wp,
                                              const float* __restrict__ bp,
                                              float* __restrict__ out) {
    __shared__ float As[16][64];
    __shared__ float Bs[16][128];
    int row0 = blockIdx.y * 64;
    int col0 = blockIdx.x * 128;
    int tid = threadIdx.x;
    int tx = tid & 15, ty = tid >> 4;
    float acc[4][8];
    #pragma unroll
    for (int i = 0; i < 4; i++)
        #pragma unroll
        for (int j = 0; j < 8; j++) acc[i][j] = 0.f;

    for (int k0 = 0; k0 < HID; k0 += 16) {
        {
            int r = tid >> 2, kq = (tid & 3) << 2;
            float4 v = *(const float4*)&g_Hout[(size_t)(row0 + r) * HID + k0 + kq];
            As[kq+0][r] = fmaxf(v.x, 0.f);
            As[kq+1][r] = fmaxf(v.y, 0.f);
            As[kq+2][r] = fmaxf(v.z, 0.f);
            As[kq+3][r] = fmaxf(v.w, 0.f);
        }
        #pragma unroll
        for (int q = 0; q < 2; q++) {
            int idx = tid + q * 256;
            int c = idx >> 2, kq = (idx & 3) << 2;
            float4 v = *(const float4*)&Wp[(size_t)(col0 + c) * HID + k0 + kq];
            Bs[kq+0][c] = v.x;  Bs[kq+1][c] = v.y;
            Bs[kq+2][c] = v.z;  Bs[kq+3][c] = v.w;
        }
        __syncthreads();
        #pragma unroll
        for (int k = 0; k < 16; k++) {
            float4 a  = *(const float4*)&As[k][ty << 2];
            float4 b0 = *(const float4*)&Bs[k][tx << 3];
            float4 b1 = *(const float4*)&Bs[k][(tx << 3) + 4];
            float av[4] = {a.x, a.y, a.z, a.w};
            float bv[8] = {b0.x, b0.y, b0.z, b0.w, b1.x, b1.y, b1.z, b1.w};
            #pragma unroll
            for (int i = 0; i < 4; i++)
                #pragma unroll
                for (int j = 0; j < 8; j++) acc[i][j] += av[i] * bv[j];
        }
        __syncthreads();
    }
    #pragma unroll
    for (int i = 0; i < 4; i++) {
        int rg = row0 + (ty << 2) + i;
        int t = rg >> 5, b = rg & 31;
        float* orow = out + ((size_t)(b * T_STEPS + t)) * VOCAB + col0 + (tx << 3);
        #pragma unroll
        for (int j = 0; j < 8; j++)
            orow[j] = acc[i][j] + bp[col0 + (tx << 3) + j];
    }
}

// ---------------- launcher ----------------
extern "C" void kernel_launch(void* const* d_in, const int* in_sizes, int n_in,
                              void* d_out, int out_size) {
    const float* c_memory = (const float*)d_in[0];
    const int*   c_mask   = (const int*)  d_in[1];
    const float* f_memory = (const float*)d_in[2];
    const int*   f_mask   = (const int*)  d_in[3];
    const float* hidden   = (const float*)d_in[4];
    /* d_in[5] = cf_attn (unused) */
    const float* latent   = (const float*)d_in[6];
    const int*   target   = (const int*)  d_in[7];
    const float* emb      = (const float*)d_in[8];
    const float* cW_h = (const float*)d_in[9],  *cb_h = (const float*)d_in[10];
    const float* cW_m = (const float*)d_in[11], *cb_m = (const float*)d_in[12];
    const float* cW_o = (const float*)d_in[13];
    const float* fW_h = (const float*)d_in[15], *fb_h = (const float*)d_in[16];
    const float* fW_m = (const float*)d_in[17], *fb_m = (const float*)d_in[18];
    const float* fW_o = (const float*)d_in[19];
    const float* W_ih = (const float*)d_in[21], *b_ih = (const float*)d_in[22];
    const float* W_hh = (const float*)d_in[23], *b_hh = (const float*)d_in[24];
    const float* W_proj = (const float*)d_in[25], *b_proj = (const float*)d_in[26];
    float* out = (float*)d_out;

    // precompute (h-independent)
    {
        int total = 2 * S_MEM * HID * NB;
        k_prep_mem<<<(total + 255) / 256, 256>>>(c_memory, f_memory);
    }
    {
        int total = T_STEPS * EMB * NB + HID * NB + LATD * NB;
        k_prep_misc<<<(total + 255) / 256, 256>>>(hidden, latent, emb, target);
    }
    k_KT<<<(2 * S_MEM * 128) / 8, 256>>>(cW_m, cb_m, fW_m, fb_m);   // 1600 blocks
    k_GIc<<<(T_STEPS * 384) / 8, 256>>>(W_ih, b_ih);                 // 1440 blocks

    // sequential recurrence
    for (int t = 0; t < T_STEPS; t++) {
        k_q    <<<32, 256>>>(t, cW_h, cb_h, fW_h, fb_h);
        k_score<<<50, 256>>>(cW_o, fW_o);
        k_ctx  <<<16, 256>>>(c_mask, f_mask);
        k_gru  <<<128, 256>>>(t, W_ih, W_hh, b_hh);
    }

    // batched vocab projection (93% of FLOPs, fully parallel)
    dim3 pg(VOCAB / 128, (T_STEPS * NB) / 64);   // 250 x 15
    k_proj<<<pg, 256>>>(W_proj, b_proj, out);
}

// round 2
// speedup vs baseline: 2.0078x; 2.0078x over previous
#include <cuda_runtime.h>
#include <math.h>

// Problem dims (compile-time)
#define T_STEPS 30
#define NB      32
#define S_MEM   50
#define HID     512
#define EMB     512
#define LATD    64
#define VOCAB   32000
#define GIN     1600      // E + MC + MF + LAT
#define G3H     1536      // 3*H
#define GRID_P  148       // persistent grid (1 block / SM, all co-resident)

// ---------------- device scratch ----------------
__device__ float g_memT[2][S_MEM][HID][NB];   // [side][s][m][b]
__device__ float g_KT  [2][S_MEM][HID][NB];   // attention keys
__device__ float g_embT[T_STEPS][EMB][NB];
__device__ float g_latT[LATD][NB];
__device__ float g_hT  [2][HID][NB];          // ping-pong hidden
__device__ float g_qT  [2][HID][NB];
__device__ float g_S8  [2][S_MEM][8][NB];     // score partials (8 d-chunks)
__device__ float g_ctxT[2][HID][NB];          // contexts (contiguous [1024][NB])
__device__ float g_GIc [T_STEPS][G3H][NB];
__device__ float g_Hout[T_STEPS * NB * HID];
__device__ unsigned g_bar;                    // grid barrier counter

// ---------------- helpers ----------------
__device__ __forceinline__ float fast_tanh(float x) {
    x = fminf(fmaxf(x, -15.f), 15.f);
    float e = __expf(2.f * x);
    return __fdividef(e - 1.f, e + 1.f);
}

__device__ __forceinline__ void grid_sync(unsigned* epoch) {
    __syncthreads();
    if (threadIdx.x == 0) {
        __threadfence();
        atomicAdd(&g_bar, 1u);
        *epoch += gridDim.x;
        while (atomicAdd(&g_bar, 0u) < *epoch) {}
    }
    __syncthreads();
}

__global__ void k_reset() { g_bar = 0u; }

// ---------------- precompute ----------------

__global__ void k_prep_mem(const float* __restrict__ cmem, const float* __restrict__ fmem) {
    int i = blockIdx.x * blockDim.x + threadIdx.x;
    const int total = 2 * S_MEM * HID * NB;
    if (i >= total) return;
    int b = i & 31;
    int m = (i >> 5) & 511;
    int s = (i >> 14) % S_MEM;
    int side = i / (S_MEM * HID * NB);
    const float* src = side ? fmem : cmem;
    g_memT[side][s][m][b] = src[(s * NB + b) * HID + m];
}

__global__ void k_prep_misc(const float* __restrict__ hidden, const float* __restrict__ latent,
                            const float* __restrict__ emb, const int* __restrict__ target) {
    int i = blockIdx.x * blockDim.x + threadIdx.x;
    const int N1 = T_STEPS * EMB * NB;
    const int N2 = HID * NB;
    const int N3 = LATD * NB;
    if (i < N1) {
        int b = i & 31; int e = (i >> 5) & 511; int t = i >> 14;
        int tok = (t == 0) ? 1 : target[(t - 1) * NB + b];
        g_embT[t][e][b] = emb[(size_t)tok * EMB + e];
    } else if (i < N1 + N2) {
        int j = i - N1; int b = j & 31; int m = j >> 5;
        g_hT[0][m][b] = hidden[b * HID + m];
    } else if (i < N1 + N2 + N3) {
        int j = i - N1 - N2; int b = j & 31; int l = j >> 5;
        g_latT[l][b] = latent[b * LATD + l];
    }
}

// KT: warp = (side, s-group of 5, 4 d's). Weight chunk reused across 5 s.
__global__ void __launch_bounds__(256) k_KT2(const float* __restrict__ cW, const float* __restrict__ cb,
                                             const float* __restrict__ fW, const float* __restrict__ fb) {
    int w    = (blockIdx.x * blockDim.x + threadIdx.x) >> 5;
    int lane = threadIdx.x & 31;
    if (w >= 2560) return;
    int dgrp = w & 127;
    int sg   = (w >> 7) % 10;
    int side = w / 1280;
    const float* W  = side ? fW : cW;
    const float* bb = side ? fb : cb;
    int d0 = dgrp * 4, s0 = sg * 5;
    float acc[4][5];
    #pragma unroll
    for (int j = 0; j < 4; j++)
        #pragma unroll
        for (int i = 0; i < 5; i++) acc[j][i] = 0.f;

    #pragma unroll 2
    for (int m = 0; m < HID; m += 4) {
        float4 w0 = __ldg((const float4*)&W[(d0+0)*HID + m]);
        float4 w1 = __ldg((const float4*)&W[(d0+1)*HID + m]);
        float4 w2 = __ldg((const float4*)&W[(d0+2)*HID + m]);
        float4 w3 = __ldg((const float4*)&W[(d0+3)*HID + m]);
        #pragma unroll
        for (int i = 0; i < 5; i++) {
            float x0 = g_memT[side][s0+i][m+0][lane];
            float x1 = g_memT[side][s0+i][m+1][lane];
            float x2 = g_memT[side][s0+i][m+2][lane];
            float x3 = g_memT[side][s0+i][m+3][lane];
            acc[0][i] += w0.x*x0 + w0.y*x1 + w0.z*x2 + w0.w*x3;
            acc[1][i] += w1.x*x0 + w1.y*x1 + w1.z*x2 + w1.w*x3;
            acc[2][i] += w2.x*x0 + w2.y*x1 + w2.z*x2 + w2.w*x3;
            acc[3][i] += w3.x*x0 + w3.y*x1 + w3.z*x2 + w3.w*x3;
        }
    }
    #pragma unroll
    for (int j = 0; j < 4; j++) {
        float bj = bb[d0+j];
        #pragma unroll
        for (int i = 0; i < 5; i++)
            g_KT[side][s0+i][d0+j][lane] = acc[j][i] + bj;
    }
}

// GIc: warp = (4 j's, t-group of 5). Weight chunk reused across 5 t.
__global__ void __launch_bounds__(256) k_GIc2(const float* __restrict__ W_ih, const float* __restrict__ b_ih) {
    int w    = (blockIdx.x * blockDim.x + threadIdx.x) >> 5;
    int lane = threadIdx.x & 31;
    if (w >= 2304) return;
    int jgrp = w % 384;
    int tg   = w / 384;
    int j0 = jgrp * 4, t0 = tg * 5;
    const float* r0 = W_ih + (size_t)(j0+0)*GIN;
    const float* r1 = W_ih + (size_t)(j0+1)*GIN;
    const float* r2 = W_ih + (size_t)(j0+2)*GIN;
    const float* r3 = W_ih + (size_t)(j0+3)*GIN;
    float acc[4][5];
    #pragma unroll
    for (int j = 0; j < 4; j++)
        #pragma unroll
        for (int i = 0; i < 5; i++) acc[j][i] = 0.f;

    #pragma unroll 2
    for (int e = 0; e < EMB; e += 4) {
        float4 w0 = __ldg((const float4*)&r0[e]);
        float4 w1 = __ldg((const float4*)&r1[e]);
        float4 w2 = __ldg((const float4*)&r2[e]);
        float4 w3 = __ldg((const float4*)&r3[e]);
        #pragma unroll
        for (int i = 0; i < 5; i++) {
            float x0 = g_embT[t0+i][e+0][lane];
            float x1 = g_embT[t0+i][e+1][lane];
            float x2 = g_embT[t0+i][e+2][lane];
            float x3 = g_embT[t0+i][e+3][lane];
            acc[0][i] += w0.x*x0 + w0.y*x1 + w0.z*x2 + w0.w*x3;
            acc[1][i] += w1.x*x0 + w1.y*x1 + w1.z*x2 + w1.w*x3;
            acc[2][i] += w2.x*x0 + w2.y*x1 + w2.z*x2 + w2.w*x3;
            acc[3][i] += w3.x*x0 + w3.y*x1 + w3.z*x2 + w3.w*x3;
        }
    }
    #pragma unroll
    for (int l = 0; l < LATD; l += 4) {
        float4 w0 = __ldg((const float4*)&r0[1536 + l]);
        float4 w1 = __ldg((const float4*)&r1[1536 + l]);
        float4 w2 = __ldg((const float4*)&r2[1536 + l]);
        float4 w3 = __ldg((const float4*)&r3[1536 + l]);
        float x0 = g_latT[l+0][lane];
        float x1 = g_latT[l+1][lane];
        float x2 = g_latT[l+2][lane];
        float x3 = g_latT[l+3][lane];
        #pragma unroll
        for (int i = 0; i < 5; i++) {
            acc[0][i] += w0.x*x0 + w0.y*x1 + w0.z*x2 + w0.w*x3;
            acc[1][i] += w1.x*x0 + w1.y*x1 + w1.z*x2 + w1.w*x3;
            acc[2][i] += w2.x*x0 + w2.y*x1 + w2.z*x2 + w2.w*x3;
            acc[3][i] += w3.x*x0 + w3.y*x1 + w3.z*x2 + w3.w*x3;
        }
    }
    #pragma unroll
    for (int j = 0; j < 4; j++) {
        float bj = b_ih[j0+j];
        #pragma unroll
        for (int i = 0; i < 5; i++)
            g_GIc[t0+i][j0+j][lane] = acc[j][i] + bj;
    }
}

// ---------------- persistent recurrence (one launch, 30 steps) ----------------
__global__ void __launch_bounds__(256, 1) k_recur(
        const float* __restrict__ cW_h, const float* __restrict__ cb_h,
        const float* __restrict__ fW_h, const float* __restrict__ fb_h,
        const float* __restrict__ cW_o, const float* __restrict__ fW_o,
        const int* __restrict__ cmask, const int* __restrict__ fmask,
        const float* __restrict__ W_ih, const float* __restrict__ W_hh,
        const float* __restrict__ b_hh) {
    __shared__ float red[6][4][NB];
    unsigned epoch = 0;
    int tid  = threadIdx.x;
    int lane = tid & 31;
    int wIn  = tid >> 5;
    int gw   = blockIdx.x * 8 + wIn;

    for (int t = 0; t < T_STEPS; t++) {
        int cur = t & 1;
        // ---- P1: q = h @ W_h.T + b_h (both sides); 256 warps ----
        if (gw < 256) {
            int side = gw >> 7, dgrp = gw & 127, d0 = dgrp * 4;
            const float* W  = side ? fW_h : cW_h;
            const float* bb = side ? fb_h : cb_h;
            float a0 = bb[d0], a1 = bb[d0+1], a2 = bb[d0+2], a3 = bb[d0+3];
            const float* x = &g_hT[cur][0][lane];
            #pragma unroll 4
            for (int m = 0; m < HID; m += 4) {
                float4 w0 = __ldg((const float4*)&W[(d0+0)*HID + m]);
                float4 w1 = __ldg((const float4*)&W[(d0+1)*HID + m]);
                float4 w2 = __ldg((const float4*)&W[(d0+2)*HID + m]);
                float4 w3 = __ldg((const float4*)&W[(d0+3)*HID + m]);
                float x0 = __ldcg(&x[(m+0)*NB]);
                float x1 = __ldcg(&x[(m+1)*NB]);
                float x2 = __ldcg(&x[(m+2)*NB]);
                float x3 = __ldcg(&x[(m+3)*NB]);
                a0 += w0.x*x0 + w0.y*x1 + w0.z*x2 + w0.w*x3;
                a1 += w1.x*x0 + w1.y*x1 + w1.z*x2 + w1.w*x3;
                a2 += w2.x*x0 + w2.y*x1 + w2.z*x2 + w2.w*x3;
                a3 += w3.x*x0 + w3.y*x1 + w3.z*x2 + w3.w*x3;
            }
            g_qT[side][d0+0][lane] = a0;
            g_qT[side][d0+1][lane] = a1;
            g_qT[side][d0+2][lane] = a2;
            g_qT[side][d0+3][lane] = a3;
        }
        grid_sync(&epoch);

        // ---- P2: score partials; 800 warps (side, s, 8 d-chunks of 64) ----
        if (gw < 800) {
            int side = gw / 400, rem = gw % 400;
            int s = rem >> 3, c = rem & 7, d0 = c * 64;
            const float* wo = side ? fW_o : cW_o;
            const float* qp = &g_qT[side][0][lane];
            const float* kp = &g_KT[side][s][0][lane];
            float acc0 = 0.f, acc1 = 0.f;
            #pragma unroll 4
            for (int d = d0; d < d0 + 64; d += 2) {
                float v0 = __ldcg(&qp[d*NB])     + __ldg(&kp[d*NB]);
                float v1 = __ldcg(&qp[(d+1)*NB]) + __ldg(&kp[(d+1)*NB]);
                acc0 += fast_tanh(v0) * __ldg(&wo[d]);
                acc1 += fast_tanh(v1) * __ldg(&wo[d+1]);
            }
            g_S8[side][s][c][lane] = acc0 + acc1;
        }
        grid_sync(&epoch);

        // ---- P3: softmax + context; 128 warps (side, 8 m's each) ----
        if (gw < 128) {
            int side = gw >> 6, m0 = (gw & 63) * 8;
            const int* mask = side ? fmask : cmask;
            float a[S_MEM];
            float mx = -1e30f;
            #pragma unroll
            for (int s = 0; s < S_MEM; s++) {
                float v = -1e30f;
                if (__ldg(&mask[s*NB + lane]) != 0) {
                    v = 0.f;
                    #pragma unroll
                    for (int c = 0; c < 8; c++) v += __ldcg(&g_S8[side][s][c][lane]);
                }
                a[s] = v;
                mx = fmaxf(mx, v);
            }
            float sum = 0.f;
            #pragma unroll
            for (int s = 0; s < S_MEM; s++) { a[s] = __expf(a[s] - mx); sum += a[s]; }
            float inv = __fdividef(1.f, sum);
            #pragma unroll
            for (int j = 0; j < 8; j++) {
                int m = m0 + j;
                float acc = 0.f;
                #pragma unroll
                for (int s = 0; s < S_MEM; s++) acc += a[s] * __ldg(&g_memT[side][s][m][lane]);
                g_ctxT[side][m][lane] = acc * inv;
            }
        }
        grid_sync(&epoch);

        // ---- P4: GRU gates + update; blocks 0..127 ----
        if (blockIdx.x < 128) {
            int hloc = wIn & 3;
            int half = wIn >> 2;
            int hidx = blockIdx.x * 4 + hloc;
            const float* ctx = &g_ctxT[0][0][0];       // [1024][NB]
            const float* hTc = &g_hT[cur][0][0];
            float ir = 0.f, iz = 0.f, inn = 0.f;
            const float* Wr = W_ih + (size_t)(hidx)        * GIN + 512;
            const float* Wz = W_ih + (size_t)(512 + hidx)  * GIN + 512;
            const float* Wn = W_ih + (size_t)(1024 + hidx) * GIN + 512;
            int kc0 = half * 512;
            #pragma unroll 4
            for (int k = kc0; k < kc0 + 512; k += 4) {
                float4 wr = __ldg((const float4*)&Wr[k]);
                float4 wz = __ldg((const float4*)&Wz[k]);
                float4 wn = __ldg((const float4*)&Wn[k]);
                float x0 = __ldcg(&ctx[(k+0)*NB + lane]);
                float x1 = __ldcg(&ctx[(k+1)*NB + lane]);
                float x2 = __ldcg(&ctx[(k+2)*NB + lane]);
                float x3 = __ldcg(&ctx[(k+3)*NB + lane]);
                ir  += wr.x*x0 + wr.y*x1 + wr.z*x2 + wr.w*x3;
                iz  += wz.x*x0 + wz.y*x1 + wz.z*x2 + wz.w*x3;
                inn += wn.x*x0 + wn.y*x1 + wn.z*x2 + wn.w*x3;
            }
            float hr = 0.f, hz = 0.f, hn = 0.f;
            const float* Ur = W_hh + (size_t)(hidx)        * HID;
            const float* Uz = W_hh + (size_t)(512 + hidx)  * HID;
            const float* Un = W_hh + (size_t)(1024 + hidx) * HID;
            int kh0 = half * 256;
            #pragma unroll 4
            for (int k = kh0; k < kh0 + 256; k += 4) {
                float4 wr = __ldg((const float4*)&Ur[k]);
                float4 wz = __ldg((const float4*)&Uz[k]);
                float4 wn = __ldg((const float4*)&Un[k]);
                float x0 = __ldcg(&hTc[(k+0)*NB + lane]);
                float x1 = __ldcg(&hTc[(k+1)*NB + lane]);
                float x2 = __ldcg(&hTc[(k+2)*NB + lane]);
                float x3 = __ldcg(&hTc[(k+3)*NB + lane]);
                hr += wr.x*x0 + wr.y*x1 + wr.z*x2 + wr.w*x3;
                hz += wz.x*x0 + wz.y*x1 + wz.z*x2 + wz.w*x3;
                hn += wn.x*x0 + wn.y*x1 + wn.z*x2 + wn.w*x3;
            }
            if (half == 1) {
                red[0][hloc][lane] = ir;  red[1][hloc][lane] = iz;  red[2][hloc][lane] = inn;
                red[3][hloc][lane] = hr;  red[4][hloc][lane] = hz;  red[5][hloc][lane] = hn;
            }
            __syncthreads();
            if (half == 0) {
                ir  += red[0][hloc][lane] + __ldg(&g_GIc[t][hidx][lane]);
                iz  += red[1][hloc][lane] + __ldg(&g_GIc[t][512 + hidx][lane]);
                inn += red[2][hloc][lane] + __ldg(&g_GIc[t][1024 + hidx][lane]);
                hr  += red[3][hloc][lane] + __ldg(&b_hh[hidx]);
                hz  += red[4][hloc][lane] + __ldg(&b_hh[512 + hidx]);
                hn  += red[5][hloc][lane] + __ldg(&b_hh[1024 + hidx]);
                float r = __fdividef(1.f, 1.f + __expf(-(ir + hr)));
                float z = __fdividef(1.f, 1.f + __expf(-(iz + hz)));
                float n = fast_tanh(inn + r * hn);
                float ho = __ldcg(&hTc[hidx * NB + lane]);
                float hnew = (1.f - z) * n + z * ho;
                g_hT[cur ^ 1][hidx][lane] = hnew;
                g_Hout[((size_t)t * NB + lane) * HID + hidx] = hnew;
            }
        }
        grid_sync(&epoch);
    }
}

// ---------------- final projection: [960,512] x [512,32000] ----------------
// 128x128 tile, BK=16, 256 threads, 8x8 micro-tile.
__global__ void __launch_bounds__(256) k_proj(const float* __restrict__ Wp,
                                              const float* __restrict__ bp,
                                              float* __restrict__ out) {
    __shared__ float As[16][128];
    __shared__ float Bs[16][128];
    int row0 = blockIdx.y * 128;
    int col0 = blockIdx.x * 128;
    int tid = threadIdx.x;
    int tx = tid & 15, ty = tid >> 4;
    float acc[8][8];
    #pragma unroll
    for (int i = 0; i < 8; i++)
        #pragma unroll
        for (int j = 0; j < 8; j++) acc[i][j] = 0.f;

    for (int k0 = 0; k0 < HID; k0 += 16) {
        #pragma unroll
        for (int q = 0; q < 2; q++) {
            int idx = tid + q * 256;
            int r = idx >> 2, kq = (idx & 3) << 2;
            int row = row0 + r;
            float4 v = make_float4(0.f, 0.f, 0.f, 0.f);
            if (row < T_STEPS * NB)
                v = *(const float4*)&g_Hout[(size_t)row * HID + k0 + kq];
            As[kq+0][r] = fmaxf(v.x, 0.f);
            As[kq+1][r] = fmaxf(v.y, 0.f);
            As[kq+2][r] = fmaxf(v.z, 0.f);
            As[kq+3][r] = fmaxf(v.w, 0.f);
        }
        #pragma unroll
        for (int q = 0; q < 2; q++) {
            int idx = tid + q * 256;
            int c = idx >> 2, kq = (idx & 3) << 2;
            float4 v = __ldg((const float4*)&Wp[(size_t)(col0 + c) * HID + k0 + kq]);
            Bs[kq+0][c] = v.x;  Bs[kq+1][c] = v.y;
            Bs[kq+2][c] = v.z;  Bs[kq+3][c] = v.w;
        }
        __syncthreads();
        #pragma unroll
        for (int k = 0; k < 16; k++) {
            float4 a0 = *(const float4*)&As[k][ty << 3];
            float4 a1 = *(const float4*)&As[k][(ty << 3) + 4];
            float4 b0 = *(const float4*)&Bs[k][tx << 3];
            float4 b1 = *(const float4*)&Bs[k][(tx << 3) + 4];
            float av[8] = {a0.x, a0.y, a0.z, a0.w, a1.x, a1.y, a1.z, a1.w};
            float bv[8] = {b0.x, b0.y, b0.z, b0.w, b1.x, b1.y, b1.z, b1.w};
            #pragma unroll
            for (int i = 0; i < 8; i++)
                #pragma unroll
                for (int j = 0; j < 8; j++) acc[i][j] += av[i] * bv[j];
        }
        __syncthreads();
    }
    #pragma unroll
    for (int i = 0; i < 8; i++) {
        int rg = row0 + (ty << 3) + i;
        if (rg >= T_STEPS * NB) break;
        int t = rg >> 5, b = rg & 31;
        float* orow = out + ((size_t)(b * T_STEPS + t)) * VOCAB + col0 + (tx << 3);
        #pragma unroll
        for (int j = 0; j < 8; j++)
            orow[j] = acc[i][j] + __ldg(&bp[col0 + (tx << 3) + j]);
    }
}

// ---------------- launcher ----------------
extern "C" void kernel_launch(void* const* d_in, const int* in_sizes, int n_in,
                              void* d_out, int out_size) {
    const float* c_memory = (const float*)d_in[0];
    const int*   c_mask   = (const int*)  d_in[1];
    const float* f_memory = (const float*)d_in[2];
    const int*   f_mask   = (const int*)  d_in[3];
    const float* hidden   = (const float*)d_in[4];
    /* d_in[5] = cf_attn (unused) */
    const float* latent   = (const float*)d_in[6];
    const int*   target   = (const int*)  d_in[7];
    const float* emb      = (const float*)d_in[8];
    const float* cW_h = (const float*)d_in[9],  *cb_h = (const float*)d_in[10];
    const float* cW_m = (const float*)d_in[11], *cb_m = (const float*)d_in[12];
    const float* cW_o = (const float*)d_in[13];
    const float* fW_h = (const float*)d_in[15], *fb_h = (const float*)d_in[16];
    const float* fW_m = (const float*)d_in[17], *fb_m = (const float*)d_in[18];
    const float* fW_o = (const float*)d_in[19];
    const float* W_ih = (const float*)d_in[21], *b_ih = (const float*)d_in[22];
    const float* W_hh = (const float*)d_in[23], *b_hh = (const float*)d_in[24];
    const float* W_proj = (const float*)d_in[25], *b_proj = (const float*)d_in[26];
    float* out = (float*)d_out;

    k_reset<<<1, 1>>>();

    {
        int total = 2 * S_MEM * HID * NB;
        k_prep_mem<<<(total + 255) / 256, 256>>>(c_memory, f_memory);
    }
    {
        int total = T_STEPS * EMB * NB + HID * NB + LATD * NB;
        k_prep_misc<<<(total + 255) / 256, 256>>>(hidden, latent, emb, target);
    }
    k_KT2<<<320, 256>>>(cW_m, cb_m, fW_m, fb_m);
    k_GIc2<<<288, 256>>>(W_ih, b_ih);

    // entire 30-step recurrence in one persistent launch
    k_recur<<<GRID_P, 256>>>(cW_h, cb_h, fW_h, fb_h, cW_o, fW_o,
                             c_mask, f_mask, W_ih, W_hh, b_hh);

    // batched vocab projection
    dim3 pg(VOCAB / 128, (T_STEPS * NB + 127) / 128);   // 250 x 8
    k_proj<<<pg, 256>>>(W_proj, b_proj, out);
}

// round 6
// speedup vs baseline: 2.4272x; 1.2089x over previous
#include <cuda_runtime.h>
#include <cuda_bf16.h>
#include <math.h>

// Problem dims
#define T_STEPS 30
#define NB      32
#define S_MEM   50
#define HID     512
#define EMB     512
#define LATD    64
#define VOCAB   32000
#define GIN     1600
#define G3H     1536
#define GRID_P  148

// ---------------- device scratch ----------------
__device__ float g_memT4[2][S_MEM][HID/4][NB][4]; // [side][s][m/4][b][4]
__device__ float g_KT  [2][S_MEM][HID][NB];
__device__ float g_embT4[T_STEPS][EMB/4][NB][4];
__device__ float g_latT4[LATD/4][NB][4];
__device__ float g_hT  [2][HID][NB];
__device__ float g_qT  [2][HID][NB];
__device__ float g_S8  [2][S_MEM][8][NB];
__device__ float g_ctxT[2][HID][NB];
__device__ float g_GIc [T_STEPS][G3H][NB];
__device__ __nv_bfloat16 g_Hhi[T_STEPS * NB * HID];  // relu(h) split, row = t*32+b
__device__ __nv_bfloat16 g_Hlo[T_STEPS * NB * HID];
__device__ __nv_bfloat16 g_Wphi[(size_t)VOCAB * HID];
__device__ __nv_bfloat16 g_Wplo[(size_t)VOCAB * HID];
__device__ unsigned g_bar;

// ---------------- helpers ----------------
__device__ __forceinline__ float fast_tanh(float x) {
    x = fminf(fmaxf(x, -15.f), 15.f);
    float e = __expf(2.f * x);
    return __fdividef(e - 1.f, e + 1.f);
}

__device__ __forceinline__ void grid_sync(unsigned* epoch) {
    __syncthreads();
    if (threadIdx.x == 0) {
        __threadfence();
        atomicAdd(&g_bar, 1u);
        *epoch += gridDim.x;
        while (atomicAdd(&g_bar, 0u) < *epoch) {}
    }
    __syncthreads();
}

__global__ void k_reset() { g_bar = 0u; }

// ---------------- precompute ----------------
__global__ void k_prep_mem(const float* __restrict__ cmem, const float* __restrict__ fmem) {
    int i = blockIdx.x * blockDim.x + threadIdx.x;
    const int total = 2 * S_MEM * HID * NB;
    if (i >= total) return;
    int b = i & 31;
    int m = (i >> 5) & 511;
    int s = (i >> 14) % S_MEM;
    int side = i / (S_MEM * HID * NB);
    const float* src = side ? fmem : cmem;
    g_memT4[side][s][m >> 2][b][m & 3] = src[(s * NB + b) * HID + m];
}

__global__ void k_prep_misc(const float* __restrict__ hidden, const float* __restrict__ latent,
                            const float* __restrict__ emb, const int* __restrict__ target) {
    int i = blockIdx.x * blockDim.x + threadIdx.x;
    const int N1 = T_STEPS * EMB * NB;
    const int N2 = HID * NB;
    const int N3 = LATD * NB;
    if (i < N1) {
        int b = i & 31; int e = (i >> 5) & 511; int t = i >> 14;
        int tok = (t == 0) ? 1 : target[(t - 1) * NB + b];
        g_embT4[t][e >> 2][b][e & 3] = emb[(size_t)tok * EMB + e];
    } else if (i < N1 + N2) {
        int j = i - N1; int b = j & 31; int m = j >> 5;
        g_hT[0][m][b] = hidden[b * HID + m];
    } else if (i < N1 + N2 + N3) {
        int j = i - N1 - N2; int b = j & 31; int l = j >> 5;
        g_latT4[l >> 2][b][l & 3] = latent[b * LATD + l];
    }
}

// W_proj -> split bf16 (hi + lo)
__global__ void k_convW(const float* __restrict__ Wp) {
    int base = (blockIdx.x * blockDim.x + threadIdx.x) * 8;
    #pragma unroll
    for (int q = 0; q < 2; q++) {
        float4 v = __ldg((const float4*)&Wp[base + q * 4]);
        float vv[4] = {v.x, v.y, v.z, v.w};
        #pragma unroll
        for (int j = 0; j < 4; j++) {
            __nv_bfloat16 hi = __float2bfloat16(vv[j]);
            float r = vv[j] - __bfloat162float(hi);
            g_Wphi[base + q * 4 + j] = hi;
            g_Wplo[base + q * 4 + j] = __float2bfloat16(r);
        }
    }
}

// KT: warp = (side, s, 4 d's). Full parallelism, float4 activation loads.
__global__ void __launch_bounds__(256) k_KT3(const float* __restrict__ cW, const float* __restrict__ cb,
                                             const float* __restrict__ fW, const float* __restrict__ fb) {
    int w    = (blockIdx.x * blockDim.x + threadIdx.x) >> 5;
    int lane = threadIdx.x & 31;
    int dgrp = w & 127;
    int s    = (w >> 7) % S_MEM;
    int side = w / (S_MEM * 128);
    if (side >= 2) return;
    const float* W  = side ? fW : cW;
    const float* bb = side ? fb : cb;
    int d0 = dgrp * 4;
    float a0 = bb[d0], a1 = bb[d0+1], a2 = bb[d0+2], a3 = bb[d0+3];
    #pragma unroll 4
    for (int m = 0; m < HID; m += 4) {
        float4 w0 = __ldg((const float4*)&W[(d0+0)*HID + m]);
        float4 w1 = __ldg((const float4*)&W[(d0+1)*HID + m]);
        float4 w2 = __ldg((const float4*)&W[(d0+2)*HID + m]);
        float4 w3 = __ldg((const float4*)&W[(d0+3)*HID + m]);
        float4 x  = *(const float4*)&g_memT4[side][s][m >> 2][lane][0];
        a0 += w0.x*x.x + w0.y*x.y + w0.z*x.z + w0.w*x.w;
        a1 += w1.x*x.x + w1.y*x.y + w1.z*x.z + w1.w*x.w;
        a2 += w2.x*x.x + w2.y*x.y + w2.z*x.z + w2.w*x.w;
        a3 += w3.x*x.x + w3.y*x.y + w3.z*x.z + w3.w*x.w;
    }
    g_KT[side][s][d0+0][lane] = a0;
    g_KT[side][s][d0+1][lane] = a1;
    g_KT[side][s][d0+2][lane] = a2;
    g_KT[side][s][d0+3][lane] = a3;
}

// GIc: warp = (4 j's, t). Full parallelism, float4 activation loads.
__global__ void __launch_bounds__(256) k_GIc3(const float* __restrict__ W_ih, const float* __restrict__ b_ih) {
    int w    = (blockIdx.x * blockDim.x + threadIdx.x) >> 5;
    int lane = threadIdx.x & 31;
    int jgrp = w % 384;
    int t    = w / 384;
    if (t >= T_STEPS) return;
    int j0 = jgrp * 4;
    float a0 = b_ih[j0], a1 = b_ih[j0+1], a2 = b_ih[j0+2], a3 = b_ih[j0+3];
    const float* r0 = W_ih + (size_t)(j0+0)*GIN;
    const float* r1 = W_ih + (size_t)(j0+1)*GIN;
    const float* r2 = W_ih + (size_t)(j0+2)*GIN;
    const float* r3 = W_ih + (size_t)(j0+3)*GIN;
    #pragma unroll 4
    for (int e = 0; e < EMB; e += 4) {
        float4 w0 = __ldg((const float4*)&r0[e]);
        float4 w1 = __ldg((const float4*)&r1[e]);
        float4 w2 = __ldg((const float4*)&r2[e]);
        float4 w3 = __ldg((const float4*)&r3[e]);
        float4 x  = *(const float4*)&g_embT4[t][e >> 2][lane][0];
        a0 += w0.x*x.x + w0.y*x.y + w0.z*x.z + w0.w*x.w;
        a1 += w1.x*x.x + w1.y*x.y + w1.z*x.z + w1.w*x.w;
        a2 += w2.x*x.x + w2.y*x.y + w2.z*x.z + w2.w*x.w;
        a3 += w3.x*x.x + w3.y*x.y + w3.z*x.z + w3.w*x.w;
    }
    #pragma unroll
    for (int l = 0; l < LATD; l += 4) {
        float4 w0 = __ldg((const float4*)&r0[1536 + l]);
        float4 w1 = __ldg((const float4*)&r1[1536 + l]);
        float4 w2 = __ldg((const float4*)&r2[1536 + l]);
        float4 w3 = __ldg((const float4*)&r3[1536 + l]);
        float4 x  = *(const float4*)&g_latT4[l >> 2][lane][0];
        a0 += w0.x*x.x + w0.y*x.y + w0.z*x.z + w0.w*x.w;
        a1 += w1.x*x.x + w1.y*x.y + w1.z*x.z + w1.w*x.w;
        a2 += w2.x*x.x + w2.y*x.y + w2.z*x.z + w2.w*x.w;
        a3 += w3.x*x.x + w3.y*x.y + w3.z*x.z + w3.w*x.w;
    }
    g_GIc[t][j0+0][lane] = a0;
    g_GIc[t][j0+1][lane] = a1;
    g_GIc[t][j0+2][lane] = a2;
    g_GIc[t][j0+3][lane] = a3;
}

// ---------------- persistent recurrence ----------------
__global__ void __launch_bounds__(256, 1) k_recur(
        const float* __restrict__ cW_h, const float* __restrict__ cb_h,
        const float* __restrict__ fW_h, const float* __restrict__ fb_h,
        const float* __restrict__ cW_o, const float* __restrict__ fW_o,
        const int* __restrict__ cmask, const int* __restrict__ fmask,
        const float* __restrict__ W_ih, const float* __restrict__ W_hh,
        const float* __restrict__ b_hh) {
    __shared__ float red[6][4][NB];
    unsigned epoch = 0;
    int tid  = threadIdx.x;
    int lane = tid & 31;
    int wIn  = tid >> 5;
    int gw   = blockIdx.x * 8 + wIn;

    for (int t = 0; t < T_STEPS; t++) {
        int cur = t & 1;
        // ---- P1: q = h @ W_h.T + b_h ----
        if (gw < 256) {
            int side = gw >> 7, dgrp = gw & 127, d0 = dgrp * 4;
            const float* W  = side ? fW_h : cW_h;
            const float* bb = side ? fb_h : cb_h;
            float a0 = bb[d0], a1 = bb[d0+1], a2 = bb[d0+2], a3 = bb[d0+3];
            const float* x = &g_hT[cur][0][lane];
            #pragma unroll 4
            for (int m = 0; m < HID; m += 4) {
                float4 w0 = __ldg((const float4*)&W[(d0+0)*HID + m]);
                float4 w1 = __ldg((const float4*)&W[(d0+1)*HID + m]);
                float4 w2 = __ldg((const float4*)&W[(d0+2)*HID + m]);
                float4 w3 = __ldg((const float4*)&W[(d0+3)*HID + m]);
                float x0 = __ldcg(&x[(m+0)*NB]);
                float x1 = __ldcg(&x[(m+1)*NB]);
                float x2 = __ldcg(&x[(m+2)*NB]);
                float x3 = __ldcg(&x[(m+3)*NB]);
                a0 += w0.x*x0 + w0.y*x1 + w0.z*x2 + w0.w*x3;
                a1 += w1.x*x0 + w1.y*x1 + w1.z*x2 + w1.w*x3;
                a2 += w2.x*x0 + w2.y*x1 + w2.z*x2 + w2.w*x3;
                a3 += w3.x*x0 + w3.y*x1 + w3.z*x2 + w3.w*x3;
            }
            g_qT[side][d0+0][lane] = a0;
            g_qT[side][d0+1][lane] = a1;
            g_qT[side][d0+2][lane] = a2;
            g_qT[side][d0+3][lane] = a3;
        }
        grid_sync(&epoch);

        // ---- P2: score partials ----
        if (gw < 800) {
            int side = gw / 400, rem = gw % 400;
            int s = rem >> 3, c = rem & 7, d0 = c * 64;
            const float* wo = side ? fW_o : cW_o;
            const float* qp = &g_qT[side][0][lane];
            const float* kp = &g_KT[side][s][0][lane];
            float acc0 = 0.f, acc1 = 0.f;
            #pragma unroll 4
            for (int d = d0; d < d0 + 64; d += 2) {
                float v0 = __ldcg(&qp[d*NB])     + __ldg(&kp[d*NB]);
                float v1 = __ldcg(&qp[(d+1)*NB]) + __ldg(&kp[(d+1)*NB]);
                acc0 += fast_tanh(v0) * __ldg(&wo[d]);
                acc1 += fast_tanh(v1) * __ldg(&wo[d+1]);
            }
            g_S8[side][s][c][lane] = acc0 + acc1;
        }
        grid_sync(&epoch);

        // ---- P3: softmax + context ----
        if (gw < 128) {
            int side = gw >> 6, m0 = (gw & 63) * 8;
            const int* mask = side ? fmask : cmask;
            float a[S_MEM];
            float mx = -1e30f;
            #pragma unroll
            for (int s = 0; s < S_MEM; s++) {
                float v = -1e30f;
                if (__ldg(&mask[s*NB + lane]) != 0) {
                    v = 0.f;
                    #pragma unroll
                    for (int c = 0; c < 8; c++) v += __ldcg(&g_S8[side][s][c][lane]);
                }
                a[s] = v;
                mx = fmaxf(mx, v);
            }
            float sum = 0.f;
            #pragma unroll
            for (int s = 0; s < S_MEM; s++) { a[s] = __expf(a[s] - mx); sum += a[s]; }
            float inv = __fdividef(1.f, sum);
            float acc[8];
            #pragma unroll
            for (int j = 0; j < 8; j++) acc[j] = 0.f;
            #pragma unroll
            for (int s = 0; s < S_MEM; s++) {
                float4 m1 = *(const float4*)&g_memT4[side][s][(m0 >> 2) + 0][lane][0];
                float4 m2 = *(const float4*)&g_memT4[side][s][(m0 >> 2) + 1][lane][0];
                acc[0] += a[s]*m1.x; acc[1] += a[s]*m1.y; acc[2] += a[s]*m1.z; acc[3] += a[s]*m1.w;
                acc[4] += a[s]*m2.x; acc[5] += a[s]*m2.y; acc[6] += a[s]*m2.z; acc[7] += a[s]*m2.w;
            }
            #pragma unroll
            for (int j = 0; j < 8; j++)
                g_ctxT[side][m0 + j][lane] = acc[j] * inv;
        }
        grid_sync(&epoch);

        // ---- P4: GRU gates + update (+ bf16 split of relu(h)) ----
        if (blockIdx.x < 128) {
            int hloc = wIn & 3;
            int half = wIn >> 2;
            int hidx = blockIdx.x * 4 + hloc;
            const float* ctx = &g_ctxT[0][0][0];
            const float* hTc = &g_hT[cur][0][0];
            float ir = 0.f, iz = 0.f, inn = 0.f;
            const float* Wr = W_ih + (size_t)(hidx)        * GIN + 512;
            const float* Wz = W_ih + (size_t)(512 + hidx)  * GIN + 512;
            const float* Wn = W_ih + (size_t)(1024 + hidx) * GIN + 512;
            int kc0 = half * 512;
            #pragma unroll 4
            for (int k = kc0; k < kc0 + 512; k += 4) {
                float4 wr = __ldg((const float4*)&Wr[k]);
                float4 wz = __ldg((const float4*)&Wz[k]);
                float4 wn = __ldg((const float4*)&Wn[k]);
                float x0 = __ldcg(&ctx[(k+0)*NB + lane]);
                float x1 = __ldcg(&ctx[(k+1)*NB + lane]);
                float x2 = __ldcg(&ctx[(k+2)*NB + lane]);
                float x3 = __ldcg(&ctx[(k+3)*NB + lane]);
                ir  += wr.x*x0 + wr.y*x1 + wr.z*x2 + wr.w*x3;
                iz  += wz.x*x0 + wz.y*x1 + wz.z*x2 + wz.w*x3;
                inn += wn.x*x0 + wn.y*x1 + wn.z*x2 + wn.w*x3;
            }
            float hr = 0.f, hz = 0.f, hn = 0.f;
            const float* Ur = W_hh + (size_t)(hidx)        * HID;
            const float* Uz = W_hh + (size_t)(512 + hidx)  * HID;
            const float* Un = W_hh + (size_t)(1024 + hidx) * HID;
            int kh0 = half * 256;
            #pragma unroll 4
            for (int k = kh0; k < kh0 + 256; k += 4) {
                float4 wr = __ldg((const float4*)&Ur[k]);
                float4 wz = __ldg((const float4*)&Uz[k]);
                float4 wn = __ldg((const float4*)&Un[k]);
                float x0 = __ldcg(&hTc[(k+0)*NB + lane]);
                float x1 = __ldcg(&hTc[(k+1)*NB + lane]);
                float x2 = __ldcg(&hTc[(k+2)*NB + lane]);
                float x3 = __ldcg(&hTc[(k+3)*NB + lane]);
                hr += wr.x*x0 + wr.y*x1 + wr.z*x2 + wr.w*x3;
                hz += wz.x*x0 + wz.y*x1 + wz.z*x2 + wz.w*x3;
                hn += wn.x*x0 + wn.y*x1 + wn.z*x2 + wn.w*x3;
            }
            if (half == 1) {
                red[0][hloc][lane] = ir;  red[1][hloc][lane] = iz;  red[2][hloc][lane] = inn;
                red[3][hloc][lane] = hr;  red[4][hloc][lane] = hz;  red[5][hloc][lane] = hn;
            }
            __syncthreads();
            if (half == 0) {
                ir  += red[0][hloc][lane] + __ldg(&g_GIc[t][hidx][lane]);
                iz  += red[1][hloc][lane] + __ldg(&g_GIc[t][512 + hidx][lane]);
                inn += red[2][hloc][lane] + __ldg(&g_GIc[t][1024 + hidx][lane]);
                hr  += red[3][hloc][lane] + __ldg(&b_hh[hidx]);
                hz  += red[4][hloc][lane] + __ldg(&b_hh[512 + hidx]);
                hn  += red[5][hloc][lane] + __ldg(&b_hh[1024 + hidx]);
                float r = __fdividef(1.f, 1.f + __expf(-(ir + hr)));
                float z = __fdividef(1.f, 1.f + __expf(-(iz + hz)));
                float n = fast_tanh(inn + r * hn);
                float ho = __ldcg(&hTc[hidx * NB + lane]);
                float hnew = (1.f - z) * n + z * ho;
                g_hT[cur ^ 1][hidx][lane] = hnew;
                // split-bf16 relu(h) for the tensor-core projection
                float hrelu = fmaxf(hnew, 0.f);
                __nv_bfloat16 hi = __float2bfloat16(hrelu);
                float resid = hrelu - __bfloat162float(hi);
                size_t rowoff = ((size_t)t * NB + lane) * HID + hidx;
                g_Hhi[rowoff] = hi;
                g_Hlo[rowoff] = __float2bfloat16(resid);
            }
        }
        grid_sync(&epoch);
    }
}

// ---------------- tensor-core projection ----------------
// out[b][t][v] = relu(h)[t*32+b] . W_proj[v] + b_proj[v]
// Split bf16, 3 passes (hi*hi + hi*lo + lo*hi), fp32 accumulate.
// Block tile 64x256, 8 warps (2x4), warp tile 32x64, K-chunk 64.
#define PSTR 88            // smem row stride in bf16 (conflict-free, 16B-aligned)
#define SM_A (64 * PSTR)
#define SM_B (256 * PSTR)
#define PROJ_SMEM ((2 * SM_A + 2 * SM_B) * 2)

__device__ __forceinline__ void mma_bf16(float* c, const unsigned* a, const unsigned* b) {
    asm volatile(
        "mma.sync.aligned.m16n8k16.row.col.f32.bf16.bf16.f32 "
        "{%0,%1,%2,%3}, {%4,%5,%6,%7}, {%8,%9}, {%0,%1,%2,%3};"
        : "+f"(c[0]), "+f"(c[1]), "+f"(c[2]), "+f"(c[3])
        : "r"(a[0]), "r"(a[1]), "r"(a[2]), "r"(a[3]), "r"(b[0]), "r"(b[1]));
}

__global__ void __launch_bounds__(256, 1) k_projT(const float* __restrict__ bp,
                                                  float* __restrict__ out) {
    extern __shared__ __nv_bfloat16 sm[];
    __nv_bfloat16* Ah = sm;
    __nv_bfloat16* Al = sm + SM_A;
    __nv_bfloat16* Bh = sm + 2 * SM_A;
    __nv_bfloat16* Bl = sm + 2 * SM_A + SM_B;

    int tid  = threadIdx.x;
    int lane = tid & 31;
    int wid  = tid >> 5;
    int warpM = wid >> 2;          // 0..1
    int warpN = wid & 3;           // 0..3
    int g  = lane >> 2;            // 0..7
    int tg = lane & 3;             // 0..3
    int row0 = blockIdx.y * 64;
    int col0 = blockIdx.x * 256;

    float acc[2][8][4];
    #pragma unroll
    for (int i = 0; i < 2; i++)
        #pragma unroll
        for (int j = 0; j < 8; j++)
            #pragma unroll
            for (int c = 0; c < 4; c++) acc[i][j][c] = 0.f;

    for (int k0 = 0; k0 < HID; k0 += 64) {
        // stage A (64x64 hi+lo)
        #pragma unroll
        for (int i = 0; i < 2; i++) {
            int idx = tid + i * 256;
            int r = idx >> 3, kq = (idx & 7) << 3;
            *(uint4*)&Ah[r * PSTR + kq] = *(const uint4*)&g_Hhi[(size_t)(row0 + r) * HID + k0 + kq];
            *(uint4*)&Al[r * PSTR + kq] = *(const uint4*)&g_Hlo[(size_t)(row0 + r) * HID + k0 + kq];
        }
        // stage B (256x64 hi+lo)
        #pragma unroll
        for (int i = 0; i < 8; i++) {
            int idx = tid + i * 256;
            int n = idx >> 3, kq = (idx & 7) << 3;
            *(uint4*)&Bh[n * PSTR + kq] = *(const uint4*)&g_Wphi[(size_t)(col0 + n) * HID + k0 + kq];
            *(uint4*)&Bl[n * PSTR + kq] = *(const uint4*)&g_Wplo[(size_t)(col0 + n) * HID + k0 + kq];
        }
        __syncthreads();

        #pragma unroll
        for (int kk = 0; kk < 64; kk += 16) {
            unsigned ah[2][4], al[2][4], bh[8][2], bl[8][2];
            #pragma unroll
            for (int fm = 0; fm < 2; fm++) {
                int r = warpM * 32 + fm * 16 + g;
                int c = kk + 2 * tg;
                ah[fm][0] = *(const unsigned*)&Ah[r * PSTR + c];
                ah[fm][1] = *(const unsigned*)&Ah[(r + 8) * PSTR + c];
                ah[fm][2] = *(const unsigned*)&Ah[r * PSTR + c + 8];
                ah[fm][3] = *(const unsigned*)&Ah[(r + 8) * PSTR + c + 8];
                al[fm][0] = *(const unsigned*)&Al[r * PSTR + c];
                al[fm][1] = *(const unsigned*)&Al[(r + 8) * PSTR + c];
                al[fm][2] = *(const unsigned*)&Al[r * PSTR + c + 8];
                al[fm][3] = *(const unsigned*)&Al[(r + 8) * PSTR + c + 8];
            }
            #pragma unroll
            for (int fn = 0; fn < 8; fn++) {
                int n = warpN * 64 + fn * 8 + g;
                int c = kk + 2 * tg;
                bh[fn][0] = *(const unsigned*)&Bh[n * PSTR + c];
                bh[fn][1] = *(const unsigned*)&Bh[n * PSTR + c + 8];
                bl[fn][0] = *(const unsigned*)&Bl[n * PSTR + c];
                bl[fn][1] = *(const unsigned*)&Bl[n * PSTR + c + 8];
            }
            #pragma unroll
            for (int fm = 0; fm < 2; fm++)
                #pragma unroll
                for (int fn = 0; fn < 8; fn++) {
                    mma_bf16(acc[fm][fn], ah[fm], bh[fn]);  // hi*hi
                    mma_bf16(acc[fm][fn], ah[fm], bl[fn]);  // hi*lo
                    mma_bf16(acc[fm][fn], al[fm], bh[fn]);  // lo*hi
                }
        }
        __syncthreads();
    }

    // epilogue: D[m=g / g+8][n=2tg, 2tg+1] per fragment
    #pragma unroll
    for (int fm = 0; fm < 2; fm++) {
        #pragma unroll
        for (int fn = 0; fn < 8; fn++) {
            int v = col0 + warpN * 64 + fn * 8 + 2 * tg;
            float b0 = __ldg(&bp[v]), b1 = __ldg(&bp[v + 1]);
            int r1 = row0 + warpM * 32 + fm * 16 + g;
            int t1 = r1 >> 5, bb1 = r1 & 31;
            float2 o1 = make_float2(acc[fm][fn][0] + b0, acc[fm][fn][1] + b1);
            *(float2*)&out[((size_t)(bb1 * T_STEPS + t1)) * VOCAB + v] = o1;
            int r2 = r1 + 8;
            int t2 = r2 >> 5, bb2 = r2 & 31;
            float2 o2 = make_float2(acc[fm][fn][2] + b0, acc[fm][fn][3] + b1);
            *(float2*)&out[((size_t)(bb2 * T_STEPS + t2)) * VOCAB + v] = o2;
        }
    }
}

// ---------------- launcher ----------------
extern "C" void kernel_launch(void* const* d_in, const int* in_sizes, int n_in,
                              void* d_out, int out_size) {
    const float* c_memory = (const float*)d_in[0];
    const int*   c_mask   = (const int*)  d_in[1];
    const float* f_memory = (const float*)d_in[2];
    const int*   f_mask   = (const int*)  d_in[3];
    const float* hidden   = (const float*)d_in[4];
    const float* latent   = (const float*)d_in[6];
    const int*   target   = (const int*)  d_in[7];
    const float* emb      = (const float*)d_in[8];
    const float* cW_h = (const float*)d_in[9],  *cb_h = (const float*)d_in[10];
    const float* cW_m = (const float*)d_in[11], *cb_m = (const float*)d_in[12];
    const float* cW_o = (const float*)d_in[13];
    const float* fW_h = (const float*)d_in[15], *fb_h = (const float*)d_in[16];
    const float* fW_m = (const float*)d_in[17], *fb_m = (const float*)d_in[18];
    const float* fW_o = (const float*)d_in[19];
    const float* W_ih = (const float*)d_in[21], *b_ih = (const float*)d_in[22];
    const float* W_hh = (const float*)d_in[23], *b_hh = (const float*)d_in[24];
    const float* W_proj = (const float*)d_in[25], *b_proj = (const float*)d_in[26];
    float* out = (float*)d_out;

    cudaFuncSetAttribute(k_projT, cudaFuncAttributeMaxDynamicSharedMemorySize, PROJ_SMEM);

    k_reset<<<1, 1>>>();
    {
        int total = 2 * S_MEM * HID * NB;
        k_prep_mem<<<(total + 255) / 256, 256>>>(c_memory, f_memory);
    }
    {
        int total = T_STEPS * EMB * NB + HID * NB + LATD * NB;
        k_prep_misc<<<(total + 255) / 256, 256>>>(hidden, latent, emb, target);
    }
    k_KT3<<<1600, 256>>>(cW_m, cb_m, fW_m, fb_m);
    k_GIc3<<<1440, 256>>>(W_ih, b_ih);
    k_convW<<<(VOCAB * HID) / (256 * 8), 256>>>(W_proj);   // 8000 blocks

    k_recur<<<GRID_P, 256>>>(cW_h, cb_h, fW_h, fb_h, cW_o, fW_o,
                             c_mask, f_mask, W_ih, W_hh, b_hh);

    dim3 pg(VOCAB / 256, (T_STEPS * NB) / 64);   // 125 x 15
    k_projT<<<pg, 256, PROJ_SMEM>>>(b_proj, out);
}

// round 8
// speedup vs baseline: 2.4553x; 1.0116x over previous
#include <cuda_runtime.h>
#include <cuda_bf16.h>
#include <math.h>

// Problem dims
#define T_STEPS 30
#define NB      32
#define S_MEM   50
#define HID     512
#define EMB     512
#define LATD    64
#define VOCAB   32000
#define GIN     1600
#define G3H     1536
#define GRID_P  148

// ---------------- device scratch ----------------
__device__ float g_memT4[2][S_MEM][HID/4][NB][4]; // [side][s][m/4][b][4]
__device__ float g_KT4 [2][S_MEM][HID/4][NB][4];  // keys, vector layout
__device__ float g_embT4[T_STEPS][EMB/4][NB][4];
__device__ float g_latT4[LATD/4][NB][4];
__device__ float g_hT4 [2][HID/4][NB][4];         // ping-pong hidden, vector layout
__device__ float g_qT4 [2][HID/4][NB][4];         // queries, vector layout
__device__ float g_S8b [2][S_MEM][NB][8];         // score partials, [lane][8]
__device__ float g_ctxT4[(2*HID)/4][NB][4];       // contexts, vector layout
__device__ float g_GIc [T_STEPS][G3H][NB];
__device__ __nv_bfloat16 g_Hhi[T_STEPS * NB * HID];  // relu(h) split, row = t*32+b
__device__ __nv_bfloat16 g_Hlo[T_STEPS * NB * HID];
__device__ __nv_bfloat16 g_Wphi[(size_t)VOCAB * HID];
__device__ __nv_bfloat16 g_Wplo[(size_t)VOCAB * HID];
__device__ unsigned g_bar;

// ---------------- helpers ----------------
__device__ __forceinline__ float fast_tanh(float x) {
    x = fminf(fmaxf(x, -15.f), 15.f);
    float e = __expf(2.f * x);
    return __fdividef(e - 1.f, e + 1.f);
}

__device__ __forceinline__ void grid_sync(unsigned* epoch) {
    __syncthreads();
    if (threadIdx.x == 0) {
        unsigned target = *epoch + gridDim.x;
        *epoch = target;
        __threadfence();
        atomicAdd(&g_bar, 1u);
        unsigned v;
        do {
            asm volatile("ld.acquire.gpu.global.u32 %0, [%1];"
                         : "=r"(v) : "l"(&g_bar) : "memory");
        } while (v < target);
    }
    __syncthreads();
}

__global__ void k_reset() { g_bar = 0u; }

// ---------------- precompute ----------------
__global__ void k_prep_mem(const float* __restrict__ cmem, const float* __restrict__ fmem) {
    int i = blockIdx.x * blockDim.x + threadIdx.x;
    const int total = 2 * S_MEM * HID * NB;
    if (i >= total) return;
    int b = i & 31;
    int m = (i >> 5) & 511;
    int s = (i >> 14) % S_MEM;
    int side = i / (S_MEM * HID * NB);
    const float* src = side ? fmem : cmem;
    g_memT4[side][s][m >> 2][b][m & 3] = src[(s * NB + b) * HID + m];
}

__global__ void k_prep_misc(const float* __restrict__ hidden, const float* __restrict__ latent,
                            const float* __restrict__ emb, const int* __restrict__ target) {
    int i = blockIdx.x * blockDim.x + threadIdx.x;
    const int N1 = T_STEPS * EMB * NB;
    const int N2 = HID * NB;
    const int N3 = LATD * NB;
    if (i < N1) {
        int b = i & 31; int e = (i >> 5) & 511; int t = i >> 14;
        int tok = (t == 0) ? 1 : target[(t - 1) * NB + b];
        g_embT4[t][e >> 2][b][e & 3] = emb[(size_t)tok * EMB + e];
    } else if (i < N1 + N2) {
        int j = i - N1; int b = j & 31; int m = j >> 5;
        g_hT4[0][m >> 2][b][m & 3] = hidden[b * HID + m];
    } else if (i < N1 + N2 + N3) {
        int j = i - N1 - N2; int b = j & 31; int l = j >> 5;
        g_latT4[l >> 2][b][l & 3] = latent[b * LATD + l];
    }
}

// W_proj -> split bf16 (hi + lo)
__global__ void k_convW(const float* __restrict__ Wp) {
    int base = (blockIdx.x * blockDim.x + threadIdx.x) * 8;
    #pragma unroll
    for (int q = 0; q < 2; q++) {
        float4 v = __ldg((const float4*)&Wp[base + q * 4]);
        float vv[4] = {v.x, v.y, v.z, v.w};
        #pragma unroll
        for (int j = 0; j < 4; j++) {
            __nv_bfloat16 hi = __float2bfloat16(vv[j]);
            float r = vv[j] - __bfloat162float(hi);
            g_Wphi[base + q * 4 + j] = hi;
            g_Wplo[base + q * 4 + j] = __float2bfloat16(r);
        }
    }
}

// KT: warp = (side, s, 4 d's). Full parallelism, float4 loads both sides.
__global__ void __launch_bounds__(256) k_KT3(const float* __restrict__ cW, const float* __restrict__ cb,
                                             const float* __restrict__ fW, const float* __restrict__ fb) {
    int w    = (blockIdx.x * blockDim.x + threadIdx.x) >> 5;
    int lane = threadIdx.x & 31;
    int dgrp = w & 127;
    int s    = (w >> 7) % S_MEM;
    int side = w / (S_MEM * 128);
    if (side >= 2) return;
    const float* W  = side ? fW : cW;
    const float* bb = side ? fb : cb;
    int d0 = dgrp * 4;
    float a0 = bb[d0], a1 = bb[d0+1], a2 = bb[d0+2], a3 = bb[d0+3];
    #pragma unroll 4
    for (int m = 0; m < HID; m += 4) {
        float4 w0 = __ldg((const float4*)&W[(d0+0)*HID + m]);
        float4 w1 = __ldg((const float4*)&W[(d0+1)*HID + m]);
        float4 w2 = __ldg((const float4*)&W[(d0+2)*HID + m]);
        float4 w3 = __ldg((const float4*)&W[(d0+3)*HID + m]);
        float4 x  = *(const float4*)&g_memT4[side][s][m >> 2][lane][0];
        a0 += w0.x*x.x + w0.y*x.y + w0.z*x.z + w0.w*x.w;
        a1 += w1.x*x.x + w1.y*x.y + w1.z*x.z + w1.w*x.w;
        a2 += w2.x*x.x + w2.y*x.y + w2.z*x.z + w2.w*x.w;
        a3 += w3.x*x.x + w3.y*x.y + w3.z*x.z + w3.w*x.w;
    }
    *(float4*)&g_KT4[side][s][d0 >> 2][lane][0] = make_float4(a0, a1, a2, a3);
}

// GIc: warp = (4 j's, t). Full parallelism, float4 activation loads.
__global__ void __launch_bounds__(256) k_GIc3(const float* __restrict__ W_ih, const float* __restrict__ b_ih) {
    int w    = (blockIdx.x * blockDim.x + threadIdx.x) >> 5;
    int lane = threadIdx.x & 31;
    int jgrp = w % 384;
    int t    = w / 384;
    if (t >= T_STEPS) return;
    int j0 = jgrp * 4;
    float a0 = b_ih[j0], a1 = b_ih[j0+1], a2 = b_ih[j0+2], a3 = b_ih[j0+3];
    const float* r0 = W_ih + (size_t)(j0+0)*GIN;
    const float* r1 = W_ih + (size_t)(j0+1)*GIN;
    const float* r2 = W_ih + (size_t)(j0+2)*GIN;
    const float* r3 = W_ih + (size_t)(j0+3)*GIN;
    #pragma unroll 4
    for (int e = 0; e < EMB; e += 4) {
        float4 w0 = __ldg((const float4*)&r0[e]);
        float4 w1 = __ldg((const float4*)&r1[e]);
        float4 w2 = __ldg((const float4*)&r2[e]);
        float4 w3 = __ldg((const float4*)&r3[e]);
        float4 x  = *(const float4*)&g_embT4[t][e >> 2][lane][0];
        a0 += w0.x*x.x + w0.y*x.y + w0.z*x.z + w0.w*x.w;
        a1 += w1.x*x.x + w1.y*x.y + w1.z*x.z + w1.w*x.w;
        a2 += w2.x*x.x + w2.y*x.y + w2.z*x.z + w2.w*x.w;
        a3 += w3.x*x.x + w3.y*x.y + w3.z*x.z + w3.w*x.w;
    }
    #pragma unroll
    for (int l = 0; l < LATD; l += 4) {
        float4 w0 = __ldg((const float4*)&r0[1536 + l]);
        float4 w1 = __ldg((const float4*)&r1[1536 + l]);
        float4 w2 = __ldg((const float4*)&r2[1536 + l]);
        float4 w3 = __ldg((const float4*)&r3[1536 + l]);
        float4 x  = *(const float4*)&g_latT4[l >> 2][lane][0];
        a0 += w0.x*x.x + w0.y*x.y + w0.z*x.z + w0.w*x.w;
        a1 += w1.x*x.x + w1.y*x.y + w1.z*x.z + w1.w*x.w;
        a2 += w2.x*x.x + w2.y*x.y + w2.z*x.z + w2.w*x.w;
        a3 += w3.x*x.x + w3.y*x.y + w3.z*x.z + w3.w*x.w;
    }
    g_GIc[t][j0+0][lane] = a0;
    g_GIc[t][j0+1][lane] = a1;
    g_GIc[t][j0+2][lane] = a2;
    g_GIc[t][j0+3][lane] = a3;
}

// ---------------- persistent recurrence ----------------
__global__ void __launch_bounds__(256, 1) k_recur(
        const float* __restrict__ cW_h, const float* __restrict__ cb_h,
        const float* __restrict__ fW_h, const float* __restrict__ fb_h,
        const float* __restrict__ cW_o, const float* __restrict__ fW_o,
        const int* __restrict__ cmask, const int* __restrict__ fmask,
        const float* __restrict__ W_ih, const float* __restrict__ W_hh,
        const float* __restrict__ b_hh) {
    __shared__ float red[6][4][NB];
    unsigned epoch = 0;
    int tid  = threadIdx.x;
    int lane = tid & 31;
    int wIn  = tid >> 5;
    int gw   = blockIdx.x * 8 + wIn;

    for (int t = 0; t < T_STEPS; t++) {
        int cur = t & 1;
        // ---- P1: q = h @ W_h.T + b_h ----
        if (gw < 256) {
            int side = gw >> 7, dgrp = gw & 127, d0 = dgrp * 4;
            const float* W  = side ? fW_h : cW_h;
            const float* bb = side ? fb_h : cb_h;
            float a0 = bb[d0], a1 = bb[d0+1], a2 = bb[d0+2], a3 = bb[d0+3];
            #pragma unroll 4
            for (int m = 0; m < HID; m += 4) {
                float4 w0 = __ldg((const float4*)&W[(d0+0)*HID + m]);
                float4 w1 = __ldg((const float4*)&W[(d0+1)*HID + m]);
                float4 w2 = __ldg((const float4*)&W[(d0+2)*HID + m]);
                float4 w3 = __ldg((const float4*)&W[(d0+3)*HID + m]);
                float4 x  = __ldcg((const float4*)&g_hT4[cur][m >> 2][lane][0]);
                a0 += w0.x*x.x + w0.y*x.y + w0.z*x.z + w0.w*x.w;
                a1 += w1.x*x.x + w1.y*x.y + w1.z*x.z + w1.w*x.w;
                a2 += w2.x*x.x + w2.y*x.y + w2.z*x.z + w2.w*x.w;
                a3 += w3.x*x.x + w3.y*x.y + w3.z*x.z + w3.w*x.w;
            }
            *(float4*)&g_qT4[side][d0 >> 2][lane][0] = make_float4(a0, a1, a2, a3);
        }
        grid_sync(&epoch);

        // ---- P2: score partials ----
        if (gw < 800) {
            int side = gw / 400, rem = gw % 400;
            int s = rem >> 3, c = rem & 7, d0 = c * 64;
            const float* wo = side ? fW_o : cW_o;
            float acc = 0.f;
            #pragma unroll 4
            for (int d = d0; d < d0 + 64; d += 4) {
                float4 q4 = __ldcg((const float4*)&g_qT4[side][d >> 2][lane][0]);
                float4 k4 = *(const float4*)&g_KT4[side][s][d >> 2][lane][0];
                float4 w4 = __ldg((const float4*)&wo[d]);
                acc += fast_tanh(q4.x + k4.x) * w4.x;
                acc += fast_tanh(q4.y + k4.y) * w4.y;
                acc += fast_tanh(q4.z + k4.z) * w4.z;
                acc += fast_tanh(q4.w + k4.w) * w4.w;
            }
            g_S8b[side][s][lane][c] = acc;
        }
        grid_sync(&epoch);

        // ---- P3: softmax + context ----
        if (gw < 128) {
            int side = gw >> 6, m0 = (gw & 63) * 8;
            const int* mask = side ? fmask : cmask;
            float a[S_MEM];
            float mx = -1e30f;
            #pragma unroll
            for (int s = 0; s < S_MEM; s++) {
                float v = -1e30f;
                if (__ldg(&mask[s*NB + lane]) != 0) {
                    float4 p0 = __ldcg((const float4*)&g_S8b[side][s][lane][0]);
                    float4 p1 = __ldcg((const float4*)&g_S8b[side][s][lane][4]);
                    v = p0.x + p0.y + p0.z + p0.w + p1.x + p1.y + p1.z + p1.w;
                }
                a[s] = v;
                mx = fmaxf(mx, v);
            }
            float sum = 0.f;
            #pragma unroll
            for (int s = 0; s < S_MEM; s++) { a[s] = __expf(a[s] - mx); sum += a[s]; }
            float inv = __fdividef(1.f, sum);
            float acc[8];
            #pragma unroll
            for (int j = 0; j < 8; j++) acc[j] = 0.f;
            #pragma unroll
            for (int s = 0; s < S_MEM; s++) {
                float4 m1 = *(const float4*)&g_memT4[side][s][(m0 >> 2) + 0][lane][0];
                float4 m2 = *(const float4*)&g_memT4[side][s][(m0 >> 2) + 1][lane][0];
                acc[0] += a[s]*m1.x; acc[1] += a[s]*m1.y; acc[2] += a[s]*m1.z; acc[3] += a[s]*m1.w;
                acc[4] += a[s]*m2.x; acc[5] += a[s]*m2.y; acc[6] += a[s]*m2.z; acc[7] += a[s]*m2.w;
            }
            int c0 = (side * HID + m0) >> 2;
            *(float4*)&g_ctxT4[c0 + 0][lane][0] =
                make_float4(acc[0]*inv, acc[1]*inv, acc[2]*inv, acc[3]*inv);
            *(float4*)&g_ctxT4[c0 + 1][lane][0] =
                make_float4(acc[4]*inv, acc[5]*inv, acc[6]*inv, acc[7]*inv);
        }
        grid_sync(&epoch);

        // ---- P4: GRU gates + update (+ bf16 split of relu(h)) ----
        if (blockIdx.x < 128) {
            int hloc = wIn & 3;
            int half = wIn >> 2;
            int hidx = blockIdx.x * 4 + hloc;
            float ir = 0.f, iz = 0.f, inn = 0.f;
            const float* Wr = W_ih + (size_t)(hidx)        * GIN + 512;
            const float* Wz = W_ih + (size_t)(512 + hidx)  * GIN + 512;
            const float* Wn = W_ih + (size_t)(1024 + hidx) * GIN + 512;
            int kc0 = half * 512;
            #pragma unroll 4
            for (int k = kc0; k < kc0 + 512; k += 4) {
                float4 wr = __ldg((const float4*)&Wr[k]);
                float4 wz = __ldg((const float4*)&Wz[k]);
                float4 wn = __ldg((const float4*)&Wn[k]);
                float4 x  = __ldcg((const float4*)&g_ctxT4[k >> 2][lane][0]);
                ir  += wr.x*x.x + wr.y*x.y + wr.z*x.z + wr.w*x.w;
                iz  += wz.x*x.x + wz.y*x.y + wz.z*x.z + wz.w*x.w;
                inn += wn.x*x.x + wn.y*x.y + wn.z*x.z + wn.w*x.w;
            }
            float hr = 0.f, hz = 0.f, hn = 0.f;
            const float* Ur = W_hh + (size_t)(hidx)        * HID;
            const float* Uz = W_hh + (size_t)(512 + hidx)  * HID;
            const float* Un = W_hh + (size_t)(1024 + hidx) * HID;
            int kh0 = half * 256;
            #pragma unroll 4
            for (int k = kh0; k < kh0 + 256; k += 4) {
                float4 wr = __ldg((const float4*)&Ur[k]);
                float4 wz = __ldg((const float4*)&Uz[k]);
                float4 wn = __ldg((const float4*)&Un[k]);
                float4 x  = __ldcg((const float4*)&g_hT4[cur][k >> 2][lane][0]);
                hr += wr.x*x.x + wr.y*x.y + wr.z*x.z + wr.w*x.w;
                hz += wz.x*x.x + wz.y*x.y + wz.z*x.z + wz.w*x.w;
                hn += wn.x*x.x + wn.y*x.y + wn.z*x.z + wn.w*x.w;
            }
            if (half == 1) {
                red[0][hloc][lane] = ir;  red[1][hloc][lane] = iz;  red[2][hloc][lane] = inn;
                red[3][hloc][lane] = hr;  red[4][hloc][lane] = hz;  red[5][hloc][lane] = hn;
            }
            __syncthreads();
            if (half == 0) {
                ir  += red[0][hloc][lane] + __ldg(&g_GIc[t][hidx][lane]);
                iz  += red[1][hloc][lane] + __ldg(&g_GIc[t][512 + hidx][lane]);
                inn += red[2][hloc][lane] + __ldg(&g_GIc[t][1024 + hidx][lane]);
                hr  += red[3][hloc][lane] + __ldg(&b_hh[hidx]);
                hz  += red[4][hloc][lane] + __ldg(&b_hh[512 + hidx]);
                hn  += red[5][hloc][lane] + __ldg(&b_hh[1024 + hidx]);
                float r = __fdividef(1.f, 1.f + __expf(-(ir + hr)));
                float z = __fdividef(1.f, 1.f + __expf(-(iz + hz)));
                float n = fast_tanh(inn + r * hn);
                float ho = __ldcg(&g_hT4[cur][hidx >> 2][lane][hidx & 3]);
                float hnew = (1.f - z) * n + z * ho;
                g_hT4[cur ^ 1][hidx >> 2][lane][hidx & 3] = hnew;
                // split-bf16 relu(h) for the tensor-core projection
                float hrelu = fmaxf(hnew, 0.f);
                __nv_bfloat16 hi = __float2bfloat16(hrelu);
                float resid = hrelu - __bfloat162float(hi);
                size_t rowoff = ((size_t)t * NB + lane) * HID + hidx;
                g_Hhi[rowoff] = hi;
                g_Hlo[rowoff] = __float2bfloat16(resid);
            }
        }
        grid_sync(&epoch);
    }
}

// ---------------- tensor-core projection ----------------
// out[b][t][v] = relu(h)[t*32+b] . W_proj[v] + b_proj[v]
// Split bf16, 3 passes (hi*hi + hi*lo + lo*hi), fp32 accumulate.
// Block tile 64x256, 8 warps (2x4), warp tile 32x64, K-chunk 64.
// Grid: x = 15 row-tiles (fast-varying) so co-resident blocks share W cols in L2.
#define PSTR 88            // smem row stride in bf16 (conflict-free, 16B-aligned)
#define SM_A (64 * PSTR)
#define SM_B (256 * PSTR)
#define PROJ_SMEM ((2 * SM_A + 2 * SM_B) * 2)

__device__ __forceinline__ void mma_bf16(float* c, const unsigned* a, const unsigned* b) {
    asm volatile(
        "mma.sync.aligned.m16n8k16.row.col.f32.bf16.bf16.f32 "
        "{%0,%1,%2,%3}, {%4,%5,%6,%7}, {%8,%9}, {%0,%1,%2,%3};"
        : "+f"(c[0]), "+f"(c[1]), "+f"(c[2]), "+f"(c[3])
        : "r"(a[0]), "r"(a[1]), "r"(a[2]), "r"(a[3]), "r"(b[0]), "r"(b[1]));
}

__global__ void __launch_bounds__(256, 1) k_projT(const float* __restrict__ bp,
                                                  float* __restrict__ out) {
    extern __shared__ __nv_bfloat16 sm[];
    __nv_bfloat16* Ah = sm;
    __nv_bfloat16* Al = sm + SM_A;
    __nv_bfloat16* Bh = sm + 2 * SM_A;
    __nv_bfloat16* Bl = sm + 2 * SM_A + SM_B;

    int tid  = threadIdx.x;
    int lane = tid & 31;
    int wid  = tid >> 5;
    int warpM = wid >> 2;          // 0..1
    int warpN = wid & 3;           // 0..3
    int g  = lane >> 2;            // 0..7
    int tg = lane & 3;             // 0..3
    int row0 = blockIdx.x * 64;    // 15 row-tiles, fast-varying
    int col0 = blockIdx.y * 256;   // 125 col-tiles

    float acc[2][8][4];
    #pragma unroll
    for (int i = 0; i < 2; i++)
        #pragma unroll
        for (int j = 0; j < 8; j++)
            #pragma unroll
            for (int c = 0; c < 4; c++) acc[i][j][c] = 0.f;

    for (int k0 = 0; k0 < HID; k0 += 64) {
        // stage A (64x64 hi+lo)
        #pragma unroll
        for (int i = 0; i < 2; i++) {
            int idx = tid + i * 256;
            int r = idx >> 3, kq = (idx & 7) << 3;
            *(uint4*)&Ah[r * PSTR + kq] = *(const uint4*)&g_Hhi[(size_t)(row0 + r) * HID + k0 + kq];
            *(uint4*)&Al[r * PSTR + kq] = *(const uint4*)&g_Hlo[(size_t)(row0 + r) * HID + k0 + kq];
        }
        // stage B (256x64 hi+lo)
        #pragma unroll
        for (int i = 0; i < 8; i++) {
            int idx = tid + i * 256;
            int n = idx >> 3, kq = (idx & 7) << 3;
            *(uint4*)&Bh[n * PSTR + kq] = *(const uint4*)&g_Wphi[(size_t)(col0 + n) * HID + k0 + kq];
            *(uint4*)&Bl[n * PSTR + kq] = *(const uint4*)&g_Wplo[(size_t)(col0 + n) * HID + k0 + kq];
        }
        __syncthreads();

        #pragma unroll
        for (int kk = 0; kk < 64; kk += 16) {
            unsigned ah[2][4], al[2][4], bh[8][2], bl[8][2];
            #pragma unroll
            for (int fm = 0; fm < 2; fm++) {
                int r = warpM * 32 + fm * 16 + g;
                int c = kk + 2 * tg;
                ah[fm][0] = *(const unsigned*)&Ah[r * PSTR + c];
                ah[fm][1] = *(const unsigned*)&Ah[(r + 8) * PSTR + c];
                ah[fm][2] = *(const unsigned*)&Ah[r * PSTR + c + 8];
                ah[fm][3] = *(const unsigned*)&Ah[(r + 8) * PSTR + c + 8];
                al[fm][0] = *(const unsigned*)&Al[r * PSTR + c];
                al[fm][1] = *(const unsigned*)&Al[(r + 8) * PSTR + c];
                al[fm][2] = *(const unsigned*)&Al[r * PSTR + c + 8];
                al[fm][3] = *(const unsigned*)&Al[(r + 8) * PSTR + c + 8];
            }
            #pragma unroll
            for (int fn = 0; fn < 8; fn++) {
                int n = warpN * 64 + fn * 8 + g;
                int c = kk + 2 * tg;
                bh[fn][0] = *(const unsigned*)&Bh[n * PSTR + c];
                bh[fn][1] = *(const unsigned*)&Bh[n * PSTR + c + 8];
                bl[fn][0] = *(const unsigned*)&Bl[n * PSTR + c];
                bl[fn][1] = *(const unsigned*)&Bl[n * PSTR + c + 8];
            }
            #pragma unroll
            for (int fm = 0; fm < 2; fm++)
                #pragma unroll
                for (int fn = 0; fn < 8; fn++) {
                    mma_bf16(acc[fm][fn], ah[fm], bh[fn]);  // hi*hi
                    mma_bf16(acc[fm][fn], ah[fm], bl[fn]);  // hi*lo
                    mma_bf16(acc[fm][fn], al[fm], bh[fn]);  // lo*hi
                }
        }
        __syncthreads();
    }

    // epilogue: D[m=g / g+8][n=2tg, 2tg+1] per fragment
    #pragma unroll
    for (int fm = 0; fm < 2; fm++) {
        #pragma unroll
        for (int fn = 0; fn < 8; fn++) {
            int v = col0 + warpN * 64 + fn * 8 + 2 * tg;
            float b0 = __ldg(&bp[v]), b1 = __ldg(&bp[v + 1]);
            int r1 = row0 + warpM * 32 + fm * 16 + g;
            int t1 = r1 >> 5, bb1 = r1 & 31;
            float2 o1 = make_float2(acc[fm][fn][0] + b0, acc[fm][fn][1] + b1);
            *(float2*)&out[((size_t)(bb1 * T_STEPS + t1)) * VOCAB + v] = o1;
            int r2 = r1 + 8;
            int t2 = r2 >> 5, bb2 = r2 & 31;
            float2 o2 = make_float2(acc[fm][fn][2] + b0, acc[fm][fn][3] + b1);
            *(float2*)&out[((size_t)(bb2 * T_STEPS + t2)) * VOCAB + v] = o2;
        }
    }
}

// ---------------- launcher ----------------
extern "C" void kernel_launch(void* const* d_in, const int* in_sizes, int n_in,
                              void* d_out, int out_size) {
    const float* c_memory = (const float*)d_in[0];
    const int*   c_mask   = (const int*)  d_in[1];
    const float* f_memory = (const float*)d_in[2];
    const int*   f_mask   = (const int*)  d_in[3];
    const float* hidden   = (const float*)d_in[4];
    const float* latent   = (const float*)d_in[6];
    const int*   target   = (const int*)  d_in[7];
    const float* emb      = (const float*)d_in[8];
    const float* cW_h = (const float*)d_in[9],  *cb_h = (const float*)d_in[10];
    const float* cW_m = (const float*)d_in[11], *cb_m = (const float*)d_in[12];
    const float* cW_o = (const float*)d_in[13];
    const float* fW_h = (const float*)d_in[15], *fb_h = (const float*)d_in[16];
    const float* fW_m = (const float*)d_in[17], *fb_m = (const float*)d_in[18];
    const float* fW_o = (const float*)d_in[19];
    const float* W_ih = (const float*)d_in[21], *b_ih = (const float*)d_in[22];
    const float* W_hh = (const float*)d_in[23], *b_hh = (const float*)d_in[24];
    const float* W_proj = (const float*)d_in[25], *b_proj = (const float*)d_in[26];
    float* out = (float*)d_out;

    cudaFuncSetAttribute(k_projT, cudaFuncAttributeMaxDynamicSharedMemorySize, PROJ_SMEM);

    k_reset<<<1, 1>>>();
    {
        int total = 2 * S_MEM * HID * NB;
        k_prep_mem<<<(total + 255) / 256, 256>>>(c_memory, f_memory);
    }
    {
        int total = T_STEPS * EMB * NB + HID * NB + LATD * NB;
        k_prep_misc<<<(total + 255) / 256, 256>>>(hidden, latent, emb, target);
    }
    k_KT3<<<1600, 256>>>(cW_m, cb_m, fW_m, fb_m);
    k_GIc3<<<1440, 256>>>(W_ih, b_ih);
    k_convW<<<(VOCAB * HID) / (256 * 8), 256>>>(W_proj);   // 8000 blocks

    k_recur<<<GRID_P, 256>>>(cW_h, cb_h, fW_h, fb_h, cW_o, fW_o,
                             c_mask, f_mask, W_ih, W_hh, b_hh);

    dim3 pg(15, VOCAB / 256);   // x = row-tiles (fast), y = col-tiles
    k_projT<<<pg, 256, PROJ_SMEM>>>(b_proj, out);
}